// round 2
// baseline (speedup 1.0000x reference)
#include <cuda_runtime.h>
#include <math.h>

#define F      128
#define HEADS  4
#define NMAX   50000
#define GMAX   64

// ---------------- device scratch (no allocations allowed) ----------------
__device__ __align__(16) float g_h  [NMAX * F];      // dense GEMM output (h per layer)
__device__ __align__(16) float g_buf[NMAX * F];      // aggregated output / next-layer input
__device__ __align__(16) float g_as [NMAX * HEADS];
__device__ __align__(16) float g_ad [NMAX * HEADS];
__device__ __align__(16) float g_m  [NMAX * HEADS];
__device__ __align__(16) float g_s  [NMAX * HEADS];
__device__ __align__(16) float g_psum[GMAX * F];
__device__ __align__(16) float g_pmax[GMAX * F];
__device__             float g_cnt [GMAX];

// ---------------- helpers ----------------
__device__ __forceinline__ void atomicMaxFloat(float* addr, float value) {
    if (value >= 0.f) {
        atomicMax((int*)addr, __float_as_int(value));
    } else {
        atomicMin((unsigned int*)addr, __float_as_uint(value));
    }
}

__device__ __forceinline__ void redAddV4(float* p, float a, float b, float c, float d) {
    asm volatile("red.global.add.v4.f32 [%0], {%1,%2,%3,%4};"
                 :: "l"(p), "f"(a), "f"(b), "f"(c), "f"(d) : "memory");
}

// ---------------- GEMM: O[N,128] = X[N,128] @ W[128,128] ----------------
__global__ void gemm_k(const float* __restrict__ X, const float* __restrict__ W,
                       float* __restrict__ O, int N) {
    extern __shared__ float sm[];
    float* ws = sm;            // [128][128]
    float* xs = sm + F * F;    // [128][65]  (padded)

    const int tid  = threadIdx.x;
    const int row0 = blockIdx.x * 64;

    const float4* W4  = (const float4*)W;
    float4*       ws4 = (float4*)ws;
#pragma unroll
    for (int i = 0; i < 16; i++) ws4[tid + i * 256] = W4[tid + i * 256];

    const float4* X4 = (const float4*)X;
#pragma unroll
    for (int i = 0; i < 8; i++) {
        int idx = tid + i * 256;
        int r = idx >> 5, kq = idx & 31;
        float4 v = make_float4(0.f, 0.f, 0.f, 0.f);
        int gr = row0 + r;
        if (gr < N) v = X4[gr * 32 + kq];
        xs[(4 * kq + 0) * 65 + r] = v.x;
        xs[(4 * kq + 1) * 65 + r] = v.y;
        xs[(4 * kq + 2) * 65 + r] = v.z;
        xs[(4 * kq + 3) * 65 + r] = v.w;
    }
    __syncthreads();

    const int ty = tid >> 4, tx = tid & 15;
    float acc[4][8];
#pragma unroll
    for (int i = 0; i < 4; i++)
#pragma unroll
        for (int j = 0; j < 8; j++) acc[i][j] = 0.f;

#pragma unroll 4
    for (int k = 0; k < F; k++) {
        float xr[4];
#pragma unroll
        for (int i = 0; i < 4; i++) xr[i] = xs[k * 65 + ty * 4 + i];
        float4 w0 = *(const float4*)&ws[k * F + tx * 8];
        float4 w1 = *(const float4*)&ws[k * F + tx * 8 + 4];
        float wr[8] = {w0.x, w0.y, w0.z, w0.w, w1.x, w1.y, w1.z, w1.w};
#pragma unroll
        for (int i = 0; i < 4; i++)
#pragma unroll
            for (int j = 0; j < 8; j++) acc[i][j] = fmaf(xr[i], wr[j], acc[i][j]);
    }

#pragma unroll
    for (int i = 0; i < 4; i++) {
        int gr = row0 + ty * 4 + i;
        if (gr < N) {
            float4 o0 = make_float4(acc[i][0], acc[i][1], acc[i][2], acc[i][3]);
            float4 o1 = make_float4(acc[i][4], acc[i][5], acc[i][6], acc[i][7]);
            *(float4*)&O[gr * F + tx * 8]     = o0;
            *(float4*)&O[gr * F + tx * 8 + 4] = o1;
        }
    }
}

// ---------------- alpha_s / alpha_d per node (warp per node) ----------------
__global__ void alpha_k(const float* __restrict__ Hm,
                        const float* __restrict__ asr,
                        const float* __restrict__ adt, int N) {
    int w    = (blockIdx.x * blockDim.x + threadIdx.x) >> 5;
    int lane = threadIdx.x & 31;
    if (w >= N) return;
    int head = lane >> 3;
    int off  = (lane & 7) * 4;
    float4 h4 = *(const float4*)&Hm[w * F + lane * 4];
    float4 a4 = *(const float4*)&asr[head * 32 + off];
    float4 d4 = *(const float4*)&adt[head * 32 + off];
    float ps = h4.x * a4.x + h4.y * a4.y + h4.z * a4.z + h4.w * a4.w;
    float pd = h4.x * d4.x + h4.y * d4.y + h4.z * d4.z + h4.w * d4.w;
#pragma unroll
    for (int o = 4; o; o >>= 1) {
        ps += __shfl_down_sync(0xffffffffu, ps, o, 8);
        pd += __shfl_down_sync(0xffffffffu, pd, o, 8);
    }
    if ((lane & 7) == 0) {
        g_as[w * 4 + head] = ps;
        g_ad[w * 4 + head] = pd;
    }
}

// ---------------- per-layer init ----------------
__global__ void init_node_k(float* __restrict__ B, int N) {
    int i = blockIdx.x * blockDim.x + threadIdx.x;
    if (i < N * F) B[i] = 0.f;
    if (i < N * HEADS) { g_m[i] = -INFINITY; g_s[i] = 0.f; }
}

// ---------------- edge pass A: segment max ----------------
__global__ void edge_max_k(const int* __restrict__ ei, int E, int N) {
    int i = blockIdx.x * blockDim.x + threadIdx.x;
    int Et = E + N;
    if (i >= Et) return;
    int src, dst;
    if (i < E) { src = ei[i]; dst = ei[E + i]; }
    else       { src = dst = i - E; }
    float4 a = *(const float4*)&g_as[src * 4];
    float4 d = *(const float4*)&g_ad[dst * 4];
    float v[4] = {a.x + d.x, a.y + d.y, a.z + d.z, a.w + d.w};
#pragma unroll
    for (int h = 0; h < 4; h++) {
        float e = v[h] > 0.f ? v[h] : 0.2f * v[h];
        atomicMaxFloat(&g_m[dst * 4 + h], e);
    }
}

// ---------------- edge pass B: segment sum of exp ----------------
__global__ void edge_sum_k(const int* __restrict__ ei, int E, int N) {
    int i = blockIdx.x * blockDim.x + threadIdx.x;
    int Et = E + N;
    if (i >= Et) return;
    int src, dst;
    if (i < E) { src = ei[i]; dst = ei[E + i]; }
    else       { src = dst = i - E; }
    float4 a = *(const float4*)&g_as[src * 4];
    float4 d = *(const float4*)&g_ad[dst * 4];
    float4 m = *(const float4*)&g_m[dst * 4];
    float v[4] = {a.x + d.x, a.y + d.y, a.z + d.z, a.w + d.w};
    float mm[4] = {m.x, m.y, m.z, m.w};
#pragma unroll
    for (int h = 0; h < 4; h++) {
        float e = v[h] > 0.f ? v[h] : 0.2f * v[h];
        float mv = mm[h];
        if (isinf(mv)) mv = 0.f;
        atomicAdd(&g_s[dst * 4 + h], expf(e - mv));
    }
}

// ---------------- edge pass C: weighted aggregation (warp per edge) ----------------
__global__ void edge_aggr_k(const int* __restrict__ ei,
                            const float* __restrict__ Hm,
                            float* __restrict__ O, int E, int N) {
    int w    = (blockIdx.x * blockDim.x + threadIdx.x) >> 5;
    int lane = threadIdx.x & 31;
    int Et = E + N;
    if (w >= Et) return;
    int src, dst;
    if (w < E) { src = ei[w]; dst = ei[E + w]; }
    else       { src = dst = w - E; }
    int head = lane >> 3;
    float e = g_as[src * 4 + head] + g_ad[dst * 4 + head];
    e = e > 0.f ? e : 0.2f * e;
    float mv = g_m[dst * 4 + head];
    if (isinf(mv)) mv = 0.f;
    float sv = g_s[dst * 4 + head];
    float alpha = expf(e - mv) / (sv + 1e-16f);
    float4 hv = *(const float4*)&Hm[src * F + lane * 4];
    redAddV4(&O[dst * F + lane * 4],
             hv.x * alpha, hv.y * alpha, hv.z * alpha, hv.w * alpha);
}

// ---------------- bias (+optional ELU) ----------------
__global__ void bias_act_k(float* __restrict__ B, const float* __restrict__ b,
                           int N, int do_elu) {
    int i = blockIdx.x * blockDim.x + threadIdx.x;
    if (i >= N * F) return;
    float v = B[i] + b[i & (F - 1)];
    if (do_elu) v = v > 0.f ? v : expm1f(v);
    B[i] = v;
}

// ---------------- pooling ----------------
__global__ void pool_init_k() {
    int i = blockIdx.x * blockDim.x + threadIdx.x;
    if (i < GMAX * F) { g_psum[i] = 0.f; g_pmax[i] = -INFINITY; }
    if (i < GMAX) g_cnt[i] = 0.f;
}

__global__ void pool_k(const float* __restrict__ B,
                       const int* __restrict__ batch, int N) {
    int w    = (blockIdx.x * blockDim.x + threadIdx.x) >> 5;
    int lane = threadIdx.x & 31;
    if (w >= N) return;
    int g = batch[w];
    float4 v = *(const float4*)&B[w * F + lane * 4];
    redAddV4(&g_psum[g * F + lane * 4], v.x, v.y, v.z, v.w);
    atomicMaxFloat(&g_pmax[g * F + lane * 4 + 0], v.x);
    atomicMaxFloat(&g_pmax[g * F + lane * 4 + 1], v.y);
    atomicMaxFloat(&g_pmax[g * F + lane * 4 + 2], v.z);
    atomicMaxFloat(&g_pmax[g * F + lane * 4 + 3], v.w);
    if (lane == 0) atomicAdd(&g_cnt[g], 1.0f);
}

__global__ void final_k(const float* __restrict__ lw, const float* __restrict__ lb,
                        float* __restrict__ out) {
    int g    = (blockIdx.x * blockDim.x + threadIdx.x) >> 5;
    int lane = threadIdx.x & 31;
    if (g >= GMAX) return;
    float cnt = fmaxf(g_cnt[g], 1.0f);
    float acc = 0.f;
#pragma unroll
    for (int j = 0; j < 4; j++) {
        int c = lane * 4 + j;
        float mean = g_psum[g * F + c] / cnt;
        float mx = g_pmax[g * F + c];
        if (isinf(mx)) mx = 0.f;
        acc += (mean + mx) * lw[c];
    }
#pragma unroll
    for (int o = 16; o; o >>= 1) acc += __shfl_down_sync(0xffffffffu, acc, o);
    if (lane == 0) out[g] = acc + lb[0];
}

// ---------------- launcher ----------------
extern "C" void kernel_launch(void* const* d_in, const int* in_sizes, int n_in,
                              void* d_out, int out_size) {
    const float* x     = (const float*)d_in[0];
    const int*   ei    = (const int*)d_in[1];
    const int*   batch = (const int*)d_in[2];
    const float* W1    = (const float*)d_in[3];
    const float* as1   = (const float*)d_in[4];
    const float* ad1   = (const float*)d_in[5];
    const float* b1    = (const float*)d_in[6];
    const float* W2    = (const float*)d_in[7];
    const float* as2   = (const float*)d_in[8];
    const float* ad2   = (const float*)d_in[9];
    const float* b2    = (const float*)d_in[10];
    const float* lw    = (const float*)d_in[11];
    const float* lb    = (const float*)d_in[12];

    int N  = in_sizes[0] / F;
    int E  = in_sizes[1] / 2;
    int Et = E + N;

    float *hptr, *bptr;
    cudaGetSymbolAddress((void**)&hptr, g_h);
    cudaGetSymbolAddress((void**)&bptr, g_buf);

    size_t smem = (size_t)(F * F + F * 65) * sizeof(float);
    cudaFuncSetAttribute(gemm_k, cudaFuncAttributeMaxDynamicSharedMemorySize, (int)smem);

    int gemm_blocks = (N + 63) / 64;
    int node_warp_blocks = (N * 32 + 255) / 256;
    int nf_blocks = (N * F + 255) / 256;
    int edge_blocks = (Et + 255) / 256;
    int edge_warp_blocks = (int)(((long long)Et * 32 + 255) / 256);

    // ---- layer 1 ----
    gemm_k<<<gemm_blocks, 256, smem>>>(x, W1, hptr, N);
    alpha_k<<<node_warp_blocks, 256>>>(hptr, as1, ad1, N);
    init_node_k<<<nf_blocks, 256>>>(bptr, N);
    edge_max_k<<<edge_blocks, 256>>>(ei, E, N);
    edge_sum_k<<<edge_blocks, 256>>>(ei, E, N);
    edge_aggr_k<<<edge_warp_blocks, 256>>>(ei, hptr, bptr, E, N);
    bias_act_k<<<nf_blocks, 256>>>(bptr, b1, N, 1);

    // ---- layer 2 ----
    gemm_k<<<gemm_blocks, 256, smem>>>(bptr, W2, hptr, N);
    alpha_k<<<node_warp_blocks, 256>>>(hptr, as2, ad2, N);
    init_node_k<<<nf_blocks, 256>>>(bptr, N);
    edge_max_k<<<edge_blocks, 256>>>(ei, E, N);
    edge_sum_k<<<edge_blocks, 256>>>(ei, E, N);
    edge_aggr_k<<<edge_warp_blocks, 256>>>(ei, hptr, bptr, E, N);
    bias_act_k<<<nf_blocks, 256>>>(bptr, b2, N, 0);

    // ---- pooling + linear ----
    pool_init_k<<<(GMAX * F + 255) / 256, 256>>>();
    pool_k<<<node_warp_blocks, 256>>>(bptr, batch, N);
    final_k<<<(GMAX * 32 + 255) / 256, 256>>>(lw, lb, (float*)d_out);
}

// round 3
// speedup vs baseline: 1.3657x; 1.3657x over previous
#include <cuda_runtime.h>
#include <math.h>

#define F      128
#define HEADS  4
#define NMAX   50000
#define GMAX   64
#define EMAX   860000

// ---------------- device scratch ----------------
__device__ __align__(16) float g_h   [NMAX * F];
__device__ __align__(16) float g_buf [NMAX * F];
__device__ __align__(16) float g_as  [NMAX * HEADS];
__device__ __align__(16) float g_ad  [NMAX * HEADS];
__device__ __align__(16) float g_psum[GMAX * F];
__device__ __align__(16) float g_pmax[GMAX * F];
__device__             float g_cnt [GMAX];
__device__             int   g_deg [NMAX];
__device__             int   g_rowptr[NMAX + 1];
__device__             int   g_wpos[NMAX];
__device__             int   g_csrc[EMAX];

// ---------------- helpers ----------------
__device__ __forceinline__ void atomicMaxFloat(float* addr, float value) {
    if (value >= 0.f) atomicMax((int*)addr, __float_as_int(value));
    else              atomicMin((unsigned int*)addr, __float_as_uint(value));
}

__device__ __forceinline__ void redAddV4(float* p, float a, float b, float c, float d) {
    asm volatile("red.global.add.v4.f32 [%0], {%1,%2,%3,%4};"
                 :: "l"(p), "f"(a), "f"(b), "f"(c), "f"(d) : "memory");
}

// ---------------- GEMM: O[N,128] = X[N,128] @ W[128,128] ----------------
__global__ void gemm_k(const float* __restrict__ X, const float* __restrict__ W,
                       float* __restrict__ O, int N) {
    extern __shared__ float sm[];
    float* ws = sm;            // [128][128]
    float* xs = sm + F * F;    // [128][65]

    const int tid  = threadIdx.x;
    const int row0 = blockIdx.x * 64;

    const float4* W4  = (const float4*)W;
    float4*       ws4 = (float4*)ws;
#pragma unroll
    for (int i = 0; i < 16; i++) ws4[tid + i * 256] = W4[tid + i * 256];

    const float4* X4 = (const float4*)X;
#pragma unroll
    for (int i = 0; i < 8; i++) {
        int idx = tid + i * 256;
        int r = idx >> 5, kq = idx & 31;
        float4 v = make_float4(0.f, 0.f, 0.f, 0.f);
        int gr = row0 + r;
        if (gr < N) v = X4[gr * 32 + kq];
        xs[(4 * kq + 0) * 65 + r] = v.x;
        xs[(4 * kq + 1) * 65 + r] = v.y;
        xs[(4 * kq + 2) * 65 + r] = v.z;
        xs[(4 * kq + 3) * 65 + r] = v.w;
    }
    __syncthreads();

    const int ty = tid >> 4, tx = tid & 15;
    float acc[4][8];
#pragma unroll
    for (int i = 0; i < 4; i++)
#pragma unroll
        for (int j = 0; j < 8; j++) acc[i][j] = 0.f;

#pragma unroll 4
    for (int k = 0; k < F; k++) {
        float xr[4];
#pragma unroll
        for (int i = 0; i < 4; i++) xr[i] = xs[k * 65 + ty * 4 + i];
        float4 w0 = *(const float4*)&ws[k * F + tx * 8];
        float4 w1 = *(const float4*)&ws[k * F + tx * 8 + 4];
        float wr[8] = {w0.x, w0.y, w0.z, w0.w, w1.x, w1.y, w1.z, w1.w};
#pragma unroll
        for (int i = 0; i < 4; i++)
#pragma unroll
            for (int j = 0; j < 8; j++) acc[i][j] = fmaf(xr[i], wr[j], acc[i][j]);
    }

#pragma unroll
    for (int i = 0; i < 4; i++) {
        int gr = row0 + ty * 4 + i;
        if (gr < N) {
            *(float4*)&O[gr * F + tx * 8]     = make_float4(acc[i][0], acc[i][1], acc[i][2], acc[i][3]);
            *(float4*)&O[gr * F + tx * 8 + 4] = make_float4(acc[i][4], acc[i][5], acc[i][6], acc[i][7]);
        }
    }
}

// ---------------- alpha_s / alpha_d per node (warp per node) ----------------
__global__ void alpha_k(const float* __restrict__ Hm,
                        const float* __restrict__ asr,
                        const float* __restrict__ adt, int N) {
    int w    = (blockIdx.x * blockDim.x + threadIdx.x) >> 5;
    int lane = threadIdx.x & 31;
    if (w >= N) return;
    int head = lane >> 3;
    int off  = (lane & 7) * 4;
    float4 h4 = *(const float4*)&Hm[w * F + lane * 4];
    float4 a4 = *(const float4*)&asr[head * 32 + off];
    float4 d4 = *(const float4*)&adt[head * 32 + off];
    float ps = h4.x * a4.x + h4.y * a4.y + h4.z * a4.z + h4.w * a4.w;
    float pd = h4.x * d4.x + h4.y * d4.y + h4.z * d4.z + h4.w * d4.w;
#pragma unroll
    for (int o = 4; o; o >>= 1) {
        ps += __shfl_down_sync(0xffffffffu, ps, o, 8);
        pd += __shfl_down_sync(0xffffffffu, pd, o, 8);
    }
    if ((lane & 7) == 0) {
        g_as[w * 4 + head] = ps;
        g_ad[w * 4 + head] = pd;
    }
}

// ---------------- CSR build ----------------
__global__ void zero_deg_k(int N) {
    int i = blockIdx.x * blockDim.x + threadIdx.x;
    if (i < N) g_deg[i] = 0;
}

__global__ void count_k(const int* __restrict__ ei, int E, int N) {
    int i = blockIdx.x * blockDim.x + threadIdx.x;
    int Et = E + N;
    if (i >= Et) return;
    int dst = (i < E) ? ei[E + i] : (i - E);
    atomicAdd(&g_deg[dst], 1);
}

// single-block exclusive scan of g_deg[0..N) -> g_rowptr, g_wpos
__global__ void scan_k(int N) {
    __shared__ int sm[1024];
    __shared__ int carry_s;
    int tid = threadIdx.x;
    if (tid == 0) carry_s = 0;
    __syncthreads();
    for (int base = 0; base < N; base += 1024) {
        int c = carry_s;
        int i = base + tid;
        int v = (i < N) ? g_deg[i] : 0;
        sm[tid] = v;
        __syncthreads();
#pragma unroll
        for (int o = 1; o < 1024; o <<= 1) {
            int t = (tid >= o) ? sm[tid - o] : 0;
            __syncthreads();
            sm[tid] += t;
            __syncthreads();
        }
        int excl = c + sm[tid] - v;
        if (i < N) { g_rowptr[i] = excl; g_wpos[i] = excl; }
        __syncthreads();
        if (tid == 0) carry_s = c + sm[1023];
        __syncthreads();
    }
    if (tid == 0) g_rowptr[N] = carry_s;
}

__global__ void scatter_k(const int* __restrict__ ei, int E, int N) {
    int i = blockIdx.x * blockDim.x + threadIdx.x;
    int Et = E + N;
    if (i >= Et) return;
    int src, dst;
    if (i < E) { src = ei[i]; dst = ei[E + i]; }
    else       { src = dst = i - E; }
    int pos = atomicAdd(&g_wpos[dst], 1);
    g_csrc[pos] = src;
}

// ---------------- fused softmax + aggregation + bias (+ELU), warp per dst ----------------
__global__ void aggr_k(const float* __restrict__ Hm,
                       float* __restrict__ O,
                       const float* __restrict__ bias,
                       int N, int do_elu) {
    int d    = (blockIdx.x * blockDim.x + threadIdx.x) >> 5;
    int lane = threadIdx.x & 31;
    if (d >= N) return;
    int head = lane >> 3;

    float adh = g_ad[d * 4 + head];
    int i0 = g_rowptr[d];
    int i1 = g_rowptr[d + 1];

    float4 acc = make_float4(0.f, 0.f, 0.f, 0.f);
    float sw = 0.f;

    for (int i = i0; i < i1; i++) {
        int src = __ldg(&g_csrc[i]);
        float a = __ldg(&g_as[src * 4 + head]);
        float e = a + adh;
        e = e > 0.f ? e : 0.2f * e;
        float w = __expf(e);
        float4 hv = *(const float4*)&Hm[src * F + lane * 4];
        sw    += w;
        acc.x += w * hv.x;
        acc.y += w * hv.y;
        acc.z += w * hv.z;
        acc.w += w * hv.w;
    }

    float inv = 1.0f / (sw + 1e-16f);
    float4 b4 = *(const float4*)&bias[lane * 4];
    float4 o;
    o.x = acc.x * inv + b4.x;
    o.y = acc.y * inv + b4.y;
    o.z = acc.z * inv + b4.z;
    o.w = acc.w * inv + b4.w;
    if (do_elu) {
        o.x = o.x > 0.f ? o.x : expm1f(o.x);
        o.y = o.y > 0.f ? o.y : expm1f(o.y);
        o.z = o.z > 0.f ? o.z : expm1f(o.z);
        o.w = o.w > 0.f ? o.w : expm1f(o.w);
    }
    *(float4*)&O[d * F + lane * 4] = o;
}

// ---------------- pooling ----------------
__global__ void pool_init_k() {
    int i = blockIdx.x * blockDim.x + threadIdx.x;
    if (i < GMAX * F) { g_psum[i] = 0.f; g_pmax[i] = -INFINITY; }
    if (i < GMAX) g_cnt[i] = 0.f;
}

__global__ void pool_k(const float* __restrict__ B,
                       const int* __restrict__ batch, int N) {
    int w    = (blockIdx.x * blockDim.x + threadIdx.x) >> 5;
    int lane = threadIdx.x & 31;
    if (w >= N) return;
    int g = batch[w];
    float4 v = *(const float4*)&B[w * F + lane * 4];
    redAddV4(&g_psum[g * F + lane * 4], v.x, v.y, v.z, v.w);
    atomicMaxFloat(&g_pmax[g * F + lane * 4 + 0], v.x);
    atomicMaxFloat(&g_pmax[g * F + lane * 4 + 1], v.y);
    atomicMaxFloat(&g_pmax[g * F + lane * 4 + 2], v.z);
    atomicMaxFloat(&g_pmax[g * F + lane * 4 + 3], v.w);
    if (lane == 0) atomicAdd(&g_cnt[g], 1.0f);
}

__global__ void final_k(const float* __restrict__ lw, const float* __restrict__ lb,
                        float* __restrict__ out) {
    int g    = (blockIdx.x * blockDim.x + threadIdx.x) >> 5;
    int lane = threadIdx.x & 31;
    if (g >= GMAX) return;
    float cnt = fmaxf(g_cnt[g], 1.0f);
    float acc = 0.f;
#pragma unroll
    for (int j = 0; j < 4; j++) {
        int c = lane * 4 + j;
        float mean = g_psum[g * F + c] / cnt;
        float mx = g_pmax[g * F + c];
        if (isinf(mx)) mx = 0.f;
        acc += (mean + mx) * lw[c];
    }
#pragma unroll
    for (int o = 16; o; o >>= 1) acc += __shfl_down_sync(0xffffffffu, acc, o);
    if (lane == 0) out[g] = acc + lb[0];
}

// ---------------- launcher ----------------
extern "C" void kernel_launch(void* const* d_in, const int* in_sizes, int n_in,
                              void* d_out, int out_size) {
    const float* x     = (const float*)d_in[0];
    const int*   ei    = (const int*)d_in[1];
    const int*   batch = (const int*)d_in[2];
    const float* W1    = (const float*)d_in[3];
    const float* as1   = (const float*)d_in[4];
    const float* ad1   = (const float*)d_in[5];
    const float* b1    = (const float*)d_in[6];
    const float* W2    = (const float*)d_in[7];
    const float* as2   = (const float*)d_in[8];
    const float* ad2   = (const float*)d_in[9];
    const float* b2    = (const float*)d_in[10];
    const float* lw    = (const float*)d_in[11];
    const float* lb    = (const float*)d_in[12];

    int N  = in_sizes[0] / F;
    int E  = in_sizes[1] / 2;
    int Et = E + N;

    float *hptr, *bptr;
    cudaGetSymbolAddress((void**)&hptr, g_h);
    cudaGetSymbolAddress((void**)&bptr, g_buf);

    size_t smem = (size_t)(F * F + F * 65) * sizeof(float);
    cudaFuncSetAttribute(gemm_k, cudaFuncAttributeMaxDynamicSharedMemorySize, (int)smem);

    int gemm_blocks      = (N + 63) / 64;
    int node_warp_blocks = (N * 32 + 255) / 256;
    int edge_blocks      = (Et + 255) / 256;

    // ---- CSR build (topology shared by both layers) ----
    zero_deg_k<<<(N + 255) / 256, 256>>>(N);
    count_k<<<edge_blocks, 256>>>(ei, E, N);
    scan_k<<<1, 1024>>>(N);
    scatter_k<<<edge_blocks, 256>>>(ei, E, N);

    // ---- layer 1 ----
    gemm_k<<<gemm_blocks, 256, smem>>>(x, W1, hptr, N);
    alpha_k<<<node_warp_blocks, 256>>>(hptr, as1, ad1, N);
    aggr_k<<<node_warp_blocks, 256>>>(hptr, bptr, b1, N, 1);

    // ---- layer 2 ----
    gemm_k<<<gemm_blocks, 256, smem>>>(bptr, W2, hptr, N);
    alpha_k<<<node_warp_blocks, 256>>>(hptr, as2, ad2, N);
    aggr_k<<<node_warp_blocks, 256>>>(hptr, bptr, b2, N, 0);

    // ---- pooling + linear ----
    pool_init_k<<<(GMAX * F + 255) / 256, 256>>>();
    pool_k<<<node_warp_blocks, 256>>>(bptr, batch, N);
    final_k<<<(GMAX * 32 + 255) / 256, 256>>>(lw, lb, (float*)d_out);
}